// round 5
// baseline (speedup 1.0000x reference)
#include <cuda_runtime.h>
#include <cuda_bf16.h>

#define Nw 32768
#define Tc 20
#define Ec 50
#define Hc 50
#define Vc 200

typedef unsigned long long u64;

// Precomputed input-gate table, layout [dir][v][m][4gates]: even lane (role 0)
// reads gates (i,f) at m*4+0..1, odd lane (role 1) reads (g,o) at m*4+2..3.
__device__ float g_table[2 * Vc * 200];

__global__ void build_table_kernel(
    const float* __restrict__ emb,
    const float* __restrict__ Wih_f, const float* __restrict__ bih_f, const float* __restrict__ bhh_f,
    const float* __restrict__ Wih_b, const float* __restrict__ bih_b, const float* __restrict__ bhh_b)
{
    int v = blockIdx.x;        // char value 0..199
    int dir = blockIdx.y;      // 0 = forward, 1 = backward
    int j = threadIdx.x;       // gate-major index 0..199: j = gate*50 + m
    const float* Wih = dir ? Wih_b : Wih_f;
    const float* bih = dir ? bih_b : bih_f;
    const float* bhh = dir ? bhh_b : bhh_f;

    __shared__ float xs[64];
    if (j < Ec) xs[j] = (v == 0) ? 0.f : emb[v * Ec + j];  // padding_idx row zeroed
    __syncthreads();

    float a = bih[j] + bhh[j];
    const float* wr = Wih + j * Ec;
    #pragma unroll
    for (int e = 0; e < Ec; e++) a += xs[e] * wr[e];

    int gate = j / 50, m = j % 50;
    g_table[(dir * Vc + v) * 200 + m * 4 + gate] = a;
}

__device__ __forceinline__ float sigm(float x) {
    float e = __expf(-x);
    return __fdividef(1.f, 1.f + e);
}

// Packed dual-FMA: d.lane += a.lane * b.lane (two fp32 per instruction).
__device__ __forceinline__ void fma2(u64& d, u64 a, u64 b) {
    asm("fma.rn.f32x2 %0, %1, %2, %0;" : "+l"(d) : "l"(a), "l"(b));
}
__device__ __forceinline__ float hsum2(u64 v) {
    float lo, hi;
    asm("mov.b64 {%0, %1}, %2;" : "=f"(lo), "=f"(hi) : "l"(v));
    return lo + hi;
}
__device__ __forceinline__ u64 pack_lo(float x) {
    return (u64)__float_as_uint(x);   // low lane = x, high lane = 0
}

#define GROUPS_PER_BLOCK 2
#define NBLOCKS 296

__global__ __launch_bounds__(256, 2) void lstm_kernel(
    const int* __restrict__ chars, const int* __restrict__ lens,
    const float* __restrict__ Whh_f, const float* __restrict__ Whh_b,
    float* __restrict__ out)
{
    __shared__ __align__(16) float hbuf[GROUPS_PER_BLOCK][2][56];
    __shared__ int csm[GROUPS_PER_BLOCK][Tc];

    const int gid  = threadIdx.x >> 7;      // group in block (0..1), 128 threads each
    const int gtid = threadIdx.x & 127;
    const int m    = gtid >> 1;             // hidden index 0..63; m<50 active
    const int role = gtid & 1;              // 0: gates (i,f)   1: gates (g,o)
    const int mm   = (m < 50) ? m : 49;     // clamp for address safety
    const int barid = gid + 1;              // named barrier per group

    const int groups_total = gridDim.x * GROUPS_PER_BLOCK;
    const int gg = blockIdx.x * GROUPS_PER_BLOCK + gid;
    const int total_tasks = 2 * Nw;
    const int chunk = (total_tasks + groups_total - 1) / groups_total;
    int task = gg * chunk;
    const int tend = min(task + chunk, total_tasks);

    // This thread's 2 gate rows of W_hh, packed as (k, k+1) fp32 pairs.
    u64 W0[25], W1[25];

    // Uniform activation parameterization: act0 = s0*sigm(s0*g0) - b0
    //   role 0: s0=1, b0=0  -> sigmoid(gi)
    //   role 1: s0=2, b0=1  -> tanh(gG)
    const float s0 = role ? 2.f : 1.f;
    const float b0 = role ? 1.f : 0.f;

    while (task < tend) {
        const int dir = (task >= Nw) ? 1 : 0;
        const float* Whh = dir ? Whh_b : Whh_f;
        {
            const u64* p0 = (const u64*)(Whh + (100 * role + mm) * 50);
            const u64* p1 = (const u64*)(Whh + (100 * role + 50 + mm) * 50);
            #pragma unroll
            for (int k = 0; k < 25; k++) W0[k] = p0[k];
            #pragma unroll
            for (int k = 0; k < 25; k++) W1[k] = p1[k];
        }
        const int seg_end = dir ? tend : min(tend, Nw);
        const float* Gd = g_table + dir * Vc * 200;

        for (; task < seg_end; ++task) {
            const int w = task - dir * Nw;
            const int len = lens[w];

            // Stage chars + zero h buffers (protected by the barrier below)
            if (gtid < Tc) csm[gid][gtid] = chars[w * Tc + gtid];
            if (gtid < 56) { hbuf[gid][0][gtid] = 0.f; hbuf[gid][1][gtid] = 0.f; }
            asm volatile("bar.sync %0, 128;" :: "r"(barid) : "memory");

            float cst = 0.f, hlast = 0.f;
            int p = 0;
            float2 xg = make_float2(0.f, 0.f);
            if (len > 0) {
                int c0 = csm[gid][dir ? (len - 1) : 0];
                xg = *(const float2*)(Gd + c0 * 200 + mm * 4 + role * 2);
            }

            for (int s = 0; s < len; ++s) {
                u64 a0 = pack_lo(xg.x), a1 = pack_lo(xg.y);
                // Prefetch next step's input gates while FMAs run
                if (s + 1 < len) {
                    int t1 = dir ? (len - 2 - s) : (s + 1);
                    xg = *(const float2*)(Gd + csm[gid][t1] * 200 + mm * 4 + role * 2);
                }
                const float* hb = hbuf[gid][p];
                #pragma unroll
                for (int kk = 0; kk < 12; kk++) {
                    ulonglong2 hv = *(const ulonglong2*)(hb + 4 * kk); // pairs 2kk, 2kk+1
                    fma2(a0, hv.x, W0[2 * kk + 0]);
                    fma2(a1, hv.x, W1[2 * kk + 0]);
                    fma2(a0, hv.y, W0[2 * kk + 1]);
                    fma2(a1, hv.y, W1[2 * kk + 1]);
                }
                u64 ht = *(const u64*)(hb + 48);                       // (h48,h49)
                fma2(a0, ht, W0[24]);
                fma2(a1, ht, W1[24]);

                float g0 = hsum2(a0), g1 = hsum2(a1);

                float y0   = sigm(s0 * g0);
                float act0 = s0 * y0 - b0;     // role0: sig(i)   role1: tanh(g)
                float act1 = sigm(g1);         // role0: sig(f)   role1: sig(o)

                float r0 = __shfl_xor_sync(0xffffffffu, act0, 1);
                float r1 = __shfl_xor_sync(0xffffffffu, act1, 1);

                // Valid on role-0 lanes (others compute harmless garbage):
                cst = act1 * cst + act0 * r0;          // sf*c + si*tanh(g)
                float th = 2.f * sigm(2.f * cst) - 1.f; // tanh(c)
                float hn = r1 * th;                     // sig(o) * tanh(c)

                if (role == 0 && m < 50) hbuf[gid][p ^ 1][m] = hn;
                hlast = hn;
                p ^= 1;
                asm volatile("bar.sync %0, 128;" :: "r"(barid) : "memory");
            }

            if (role == 0 && m < 50) out[w * 100 + dir * 50 + m] = hlast;
        }
    }
}

extern "C" void kernel_launch(void* const* d_in, const int* in_sizes, int n_in,
                              void* d_out, int out_size) {
    const int*   chars = (const int*)d_in[0];
    const int*   lens  = (const int*)d_in[1];
    const float* emb   = (const float*)d_in[2];
    const float* Wih_f = (const float*)d_in[3];
    const float* Whh_f = (const float*)d_in[4];
    const float* bih_f = (const float*)d_in[5];
    const float* bhh_f = (const float*)d_in[6];
    const float* Wih_b = (const float*)d_in[7];
    const float* Whh_b = (const float*)d_in[8];
    const float* bih_b = (const float*)d_in[9];
    const float* bhh_b = (const float*)d_in[10];
    float* out = (float*)d_out;

    dim3 gt(Vc, 2);
    build_table_kernel<<<gt, 200>>>(emb, Wih_f, bih_f, bhh_f, Wih_b, bih_b, bhh_b);
    lstm_kernel<<<NBLOCKS, 256>>>(chars, lens, Whh_f, Whh_b, out);
}